// round 11
// baseline (speedup 1.0000x reference)
#include <cuda_runtime.h>
#include <cuda_bf16.h>
#include <stdint.h>

// Problem constants (fixed by reference: B=16, NT=4096, D=512, V=2545)
#define B_  16
#define NT_ 4096
#define D_  512
#define V_  2545
#define D_VEC (D_ / 4)               // 128 float4 per embedding row
#define NROWS (B_ * NT_)             // 65536 output rows
#define NPREP 128                    // prep blocks (8 chunks x 16 batches)
#define CHUNK (NT_ / 8)              // 512 positions per prep chunk

#define ROWS_PER_TILE 16
#define TILE_F4 (ROWS_PER_TILE * D_VEC)        // 2048 float4 = 32 KB
#define TILE_BYTES (TILE_F4 * 16)              // 32768
#define NTILES (NROWS / ROWS_PER_TILE)         // 4096 copy blocks

// Scratch (device allocations forbidden -> __device__ global)
__device__ int g_tok[NROWS];   // source token per output row (+1 applied), always in [0, V]

// ---------------------------------------------------------------------------
// Prep kernel (proven R7 config): 128 blocks x 512 threads.
//  (a) dtype probe (int64 little-endian word-pairs vs int32);
//  (b) valid-token count L_b;
//  (c) stretch mapping for this block's 512 positions -> g_tok.
// Emits tok >= 0 always (L >= 1 is guaranteed by the reference's lengths
// distribution; the L<=0 branch writes 0 as a safe impossible-case filler).
// ---------------------------------------------------------------------------
__global__ void __launch_bounds__(512)
prep_kernel(const int* __restrict__ t32) {
    const int b     = blockIdx.x >> 3;
    const int chunk = blockIdx.x & 7;
    const int tid   = threadIdx.x;

    int bad = 0;
    if (tid < 256) {
        const int lo = t32[2 * tid];
        const int hi = t32[2 * tid + 1];
        const int want_hi = (lo < 0) ? -1 : 0;
        if (hi != want_hi || lo < -1 || lo >= V_) bad = 1;
    }
    const int is64 = __syncthreads_or(bad) ? 0 : 1;
    const int stride = is64 ? 2 : 1;
    const int* row = t32 + (size_t)b * NT_ * stride;

    int cnt = 0;
    #pragma unroll
    for (int i = tid; i < NT_; i += 512)
        cnt += (row[(size_t)i * stride] >= 0);
    #pragma unroll
    for (int off = 16; off > 0; off >>= 1)
        cnt += __shfl_down_sync(0xFFFFFFFFu, cnt, off);

    __shared__ int s_part[16];
    if ((tid & 31) == 0) s_part[tid >> 5] = cnt;
    __syncthreads();
    __shared__ int s_L;
    if (tid == 0) {
        int total = 0;
        for (int w = 0; w < 16; ++w) total += s_part[w];
        s_L = total;
    }
    __syncthreads();
    const int L = s_L;

    const int p = chunk * CHUNK + tid;
    int* tok_row = g_tok + b * NT_;
    if (L <= 0) {                    // impossible per reference (lengths >= 1)
        tok_row[p] = 0;
    } else {
        const unsigned base = (unsigned)NT_ / (unsigned)L;
        const unsigned rem  = (unsigned)NT_ % (unsigned)L;
        const unsigned boundary = ((unsigned)L - rem) * base;
        unsigned j;
        if ((unsigned)p < boundary) j = (unsigned)p / base;
        else                        j = ((unsigned)L - rem) + ((unsigned)p - boundary) / (base + 1);
        int t = row[(size_t)j * stride] + 1;    // [1, V] for valid prefix
        tok_row[p] = min(max(t, 0), V_);        // hard safety clamp
    }
}

// ---------------------------------------------------------------------------
// Copy kernel: SMEM-staged stores to dodge the STG.128 LSU-issue cost.
// One block = one 16-row (32 KB) contiguous output tile.
//   1) 16 toks -> SMEM (tiny);
//   2) each of 256 threads gathers 8 float4 from emb via LDG.128 (L1 keeps
//      serving duplicate-row reads, as measured) and lays them into the SMEM
//      tile via STS.128 (conflict-free: warps write 512B-contiguous);
//   3) fence.proxy.async, then ONE cp.async.bulk S2G of 32 KB on the TMA
//      pipe — zero LSU store-issue cost.
// grid = 4096 blocks x 256 threads, 32 KB static SMEM (~7 blocks/SM).
// ---------------------------------------------------------------------------
__global__ void __launch_bounds__(256)
embed_tile_kernel(const float4* __restrict__ emb,
                  float4* __restrict__ out) {
    __shared__ alignas(128) float4 s_buf[TILE_F4];   // 32 KB
    __shared__ int s_tok[ROWS_PER_TILE];

    const int tid  = threadIdx.x;
    const int tile = blockIdx.x;

    if (tid < ROWS_PER_TILE)
        s_tok[tid] = g_tok[tile * ROWS_PER_TILE + tid];
    __syncthreads();

    // Gather 8 float4 per thread: element idx = tid + k*256 within the tile.
    // row = idx >> 7 (128 float4 per row), lane-in-row = idx & 127.
    #pragma unroll
    for (int k = 0; k < 8; ++k) {
        const int idx  = tid + k * 256;
        const int r    = idx >> 7;
        const int lane = idx & 127;
        s_buf[idx] = __ldg(emb + (size_t)s_tok[r] * D_VEC + lane);
    }

    __syncthreads();
    asm volatile("fence.proxy.async.shared::cta;" ::: "memory");

    if (tid == 0) {
        uint32_t s_addr = (uint32_t)__cvta_generic_to_shared(s_buf);
        float4* gdst = out + (size_t)tile * TILE_F4;
        asm volatile(
            "cp.async.bulk.global.shared::cta.bulk_group [%0], [%1], %2;"
            :: "l"(gdst), "r"(s_addr), "r"((unsigned)TILE_BYTES)
            : "memory");
        asm volatile("cp.async.bulk.commit_group;" ::: "memory");
        asm volatile("cp.async.bulk.wait_group 0;" ::: "memory");
    }
}

// ---------------------------------------------------------------------------
// Launch. Identify inputs by element count:
//   text: 65536 elements (int32 or int64) or 131072 int32-words; the
//         device-side probe resolves the layout.
//   emb : (2545+1)*512 = 1303552 fp32.
// ---------------------------------------------------------------------------
extern "C" void kernel_launch(void* const* d_in, const int* in_sizes, int n_in,
                              void* d_out, int out_size) {
    const int*   text = nullptr;
    const float* emb  = nullptr;
    for (int i = 0; i < n_in; ++i) {
        if (in_sizes[i] == NROWS || in_sizes[i] == 2 * NROWS)
            text = (const int*)d_in[i];
        else if (in_sizes[i] == (V_ + 1) * D_)
            emb = (const float*)d_in[i];
    }

    prep_kernel<<<NPREP, 512>>>(text);
    embed_tile_kernel<<<NTILES, 256>>>((const float4*)emb, (float4*)d_out);
    (void)out_size;
}